// round 3
// baseline (speedup 1.0000x reference)
#include <cuda_runtime.h>
#include <math.h>
#include <stdint.h>

#define TT     128
#define BB     64
#define IDIMq  256
#define CDIMq  512
#define RRq    4
#define NNq    128
#define WWq    64
#define IFACEq 471
#define EPSq   1e-6f
#define DELTAq 5e-6f
#define CATW   768

// ---------------- static device scratch ----------------
__device__ float g_G   [(size_t)TT * BB * 4 * CDIMq];  // shared by layer0/layer1 pre-gates
__device__ float g_h0  [(size_t)TT * BB * CDIMq];
__device__ float g_h1  [2 * BB * CDIMq];
__device__ float g_c0  [BB * CDIMq];
__device__ float g_c1  [BB * CDIMq];
__device__ float g_cat [(size_t)TT * BB * CATW];
__device__ float g_xi  [(size_t)TT * BB * IFACEq];

__device__ __forceinline__ float sigm(float x)  { return 1.f / (1.f + expf(-x)); }
__device__ __forceinline__ float splus(float x) { return fmaxf(x, 0.f) + log1pf(expf(-fabsf(x))); }
__device__ __forceinline__ float warp_sum(float v) {
#pragma unroll
    for (int o = 16; o; o >>= 1) v += __shfl_xor_sync(0xffffffffu, v, o);
    return v;
}
__device__ __forceinline__ float warp_max(float v) {
#pragma unroll
    for (int o = 16; o; o >>= 1) v = fmaxf(v, __shfl_xor_sync(0xffffffffu, v, o));
    return v;
}

__global__ void zero_c_kernel() {
    int i = blockIdx.x * blockDim.x + threadIdx.x;
    g_c0[i] = 0.f; g_c1[i] = 0.f;
}

// ---------------- SGEMM: C[M,N] = A[M,K] @ B[N,K]^T + bias1 (+bias2) ----------------
// 128x128 tiles; M = gridDim.y*128 exactly; N ragged (guarded); K % 8 == 0.
__global__ void __launch_bounds__(256) sgemm_bt(
    const float* __restrict__ A, int lda,
    const float* __restrict__ B, int ldb,
    float* __restrict__ C, int ldc,
    const float* __restrict__ bias1, const float* __restrict__ bias2,
    int N, int K)
{
    __shared__ float As[8][128];
    __shared__ float Bs[8][128];
    const int m0 = blockIdx.y * 128, n0 = blockIdx.x * 128;
    const int tid = threadIdx.x;
    const int lrow = tid >> 1;
    const int lk = (tid & 1) * 4;
    const int tx = tid & 15, ty = tid >> 4;

    float acc[8][8];
#pragma unroll
    for (int i = 0; i < 8; i++)
#pragma unroll
        for (int j = 0; j < 8; j++) acc[i][j] = 0.f;

    for (int k0 = 0; k0 < K; k0 += 8) {
        float4 av = *(const float4*)(A + (size_t)(m0 + lrow) * lda + k0 + lk);
        As[lk + 0][lrow] = av.x; As[lk + 1][lrow] = av.y;
        As[lk + 2][lrow] = av.z; As[lk + 3][lrow] = av.w;
        int nr = n0 + lrow;
        float4 bv = make_float4(0.f, 0.f, 0.f, 0.f);
        if (nr < N) bv = *(const float4*)(B + (size_t)nr * ldb + k0 + lk);
        Bs[lk + 0][lrow] = bv.x; Bs[lk + 1][lrow] = bv.y;
        Bs[lk + 2][lrow] = bv.z; Bs[lk + 3][lrow] = bv.w;
        __syncthreads();
#pragma unroll
        for (int k = 0; k < 8; k++) {
            float4 a0 = *(float4*)&As[k][ty * 8 + 0];
            float4 a1 = *(float4*)&As[k][ty * 8 + 4];
            float4 b0 = *(float4*)&Bs[k][tx * 8 + 0];
            float4 b1 = *(float4*)&Bs[k][tx * 8 + 4];
            float ar[8] = {a0.x, a0.y, a0.z, a0.w, a1.x, a1.y, a1.z, a1.w};
            float br[8] = {b0.x, b0.y, b0.z, b0.w, b1.x, b1.y, b1.z, b1.w};
#pragma unroll
            for (int i = 0; i < 8; i++)
#pragma unroll
                for (int j = 0; j < 8; j++) acc[i][j] += ar[i] * br[j];
        }
        __syncthreads();
    }
#pragma unroll
    for (int i = 0; i < 8; i++) {
        int m = m0 + ty * 8 + i;
#pragma unroll
        for (int j = 0; j < 8; j++) {
            int n = n0 + tx * 8 + j;
            if (n < N) {
                float v = acc[i][j] + bias1[n];
                if (bias2) v += bias2[n];
                C[(size_t)m * ldc + n] = v;
            }
        }
    }
}

// ---------------- per-step LSTM: g = Gpre + hprev @ Whh^T; gates; h,c ----------------
// grid (32 j-tiles of 16, 4 b-tiles of 16), 256 threads.
#define HSTR 516
__global__ void __launch_bounds__(256) lstm_step(
    const float* __restrict__ Gpre,   // [BB,2048] (ih + both biases)
    const float* __restrict__ hprev,  // [BB,512] or null (t==0)
    const float* __restrict__ Whh,    // [2048,512]
    float* __restrict__ hout,         // [BB,512]
    float* __restrict__ cst,          // [BB,512] in/out
    float* __restrict__ clipout)      // null, or g_cat row (stride CATW)
{
    __shared__ float hs[16 * HSTR];
    const int tid = threadIdx.x;
    const int jl = tid >> 4, bl = tid & 15;
    const int j  = blockIdx.x * 16 + jl;
    const int b  = blockIdx.y * 16 + bl;

    float a0 = 0.f, a1 = 0.f, a2 = 0.f, a3 = 0.f;
    if (hprev) {
        const float* src = hprev + (size_t)(blockIdx.y * 16) * 512;
        for (int idx = tid; idx < 16 * 128; idx += 256) {
            int rr = idx >> 7, c4 = idx & 127;
            *((float4*)(hs + rr * HSTR) + c4) = *((const float4*)(src + rr * 512) + c4);
        }
        __syncthreads();
        const float4* hp = (const float4*)(hs + bl * HSTR);
        const float4* w0 = (const float4*)(Whh + (size_t)(j)        * 512);
        const float4* w1 = (const float4*)(Whh + (size_t)(512 + j)  * 512);
        const float4* w2 = (const float4*)(Whh + (size_t)(1024 + j) * 512);
        const float4* w3 = (const float4*)(Whh + (size_t)(1536 + j) * 512);
#pragma unroll 4
        for (int k = 0; k < 128; k++) {
            float4 h = hp[k];
            float4 v0 = w0[k]; a0 += v0.x*h.x + v0.y*h.y + v0.z*h.z + v0.w*h.w;
            float4 v1 = w1[k]; a1 += v1.x*h.x + v1.y*h.y + v1.z*h.z + v1.w*h.w;
            float4 v2 = w2[k]; a2 += v2.x*h.x + v2.y*h.y + v2.z*h.z + v2.w*h.w;
            float4 v3 = w3[k]; a3 += v3.x*h.x + v3.y*h.y + v3.z*h.z + v3.w*h.w;
        }
    }
    const size_t gb = (size_t)b * 2048;
    float gi = Gpre[gb +        j] + a0;
    float gf = Gpre[gb +  512 + j] + a1;
    float gg = Gpre[gb + 1024 + j] + a2;
    float go = Gpre[gb + 1536 + j] + a3;
    int hi = b * 512 + j;
    float c = sigm(gf) * cst[hi] + sigm(gi) * tanhf(gg);
    float h = sigm(go) * tanhf(c);
    cst[hi]  = c;
    hout[hi] = h;
    if (clipout) clipout[(size_t)b * CATW + j] = fminf(fmaxf(h, -20.f), 20.f);
}

// ---------------- DNC memory module: 1 block/batch, all T steps in smem ----------------
struct MemSmem {
    float mem[NNq][WWq + 1];
    float link[NNq][NNq + 1];
    float prec[NNq], usage[NNq], ww[NNq];
    float rw[RRq][NNq], rw2[RRq][NNq], fwd[RRq][NNq], bwd[RRq][NNq], rc[RRq][NNq];
    float wc[NNq], u[NNq], su[NNq], pe[NNq], norms[NNq];
    int   rank[NNq];
    float rkeys[RRq][WWq];
    float wkey[WWq], wvec[WWq], erase[WWq];
    float rstr[RRq], fg[RRq], rknorm[RRq];
    float modes[RRq][3];
    float scal[8];
};
#define S_WSTR 0
#define S_AG   1
#define S_WG   2
#define S_KN   3
#define S_SWW  4

__global__ void __launch_bounds__(256) memory_kernel(
    const float* __restrict__ xi_all, float* __restrict__ cat)
{
    extern __shared__ __align__(16) char smraw[];
    MemSmem* s = (MemSmem*)smraw;
    const int b = blockIdx.x, tid = threadIdx.x;

    for (int i = tid; i < (int)(sizeof(MemSmem) / 4); i += 256) ((float*)smraw)[i] = 0.f;
    __syncthreads();

    for (int t = 0; t < TT; t++) {
        const float* xi = xi_all + ((size_t)t * BB + b) * IFACEq;

        // ---- parse interface ----
        { int r = tid >> 6, w = tid & 63; s->rkeys[r][w] = tanhf(xi[tid]); }
        if (tid < 64) {
            s->wkey[tid]  = tanhf(xi[260 + tid]);
            s->erase[tid] = sigm (xi[325 + tid]);
            s->wvec[tid]  = tanhf(xi[389 + tid]);
        } else if (tid < 68) s->rstr[tid - 64] = splus(xi[256 + tid - 64]);
        else if (tid < 72)   s->fg[tid - 68]   = sigm (xi[453 + tid - 68]);
        else if (tid == 72)  s->scal[S_WSTR]   = splus(xi[324]);
        else if (tid == 73)  s->scal[S_AG]     = sigm (xi[457]);
        else if (tid == 74)  s->scal[S_WG]     = sigm (xi[458]);
        else if (tid >= 80 && tid < 84) {
            int r = tid - 80;
            float x0 = xi[459 + 3*r], x1 = xi[460 + 3*r], x2 = xi[461 + 3*r];
            float m = fmaxf(x0, fmaxf(x1, x2));
            float e0 = expf(x0 - m), e1 = expf(x1 - m), e2 = expf(x2 - m);
            float inv = 1.f / (e0 + e1 + e2);
            s->modes[r][0] = e0*inv; s->modes[r][1] = e1*inv; s->modes[r][2] = e2*inv;
        }
        __syncthreads();

        // ---- usage (old ww/rw), old-mem norms, key norms ----
        if (tid < 128) {
            float us = s->usage[tid] + (1.f - s->usage[tid]) * s->ww[tid];
            float ret = 1.f;
#pragma unroll
            for (int r = 0; r < RRq; r++) ret *= (1.f - s->fg[r] * s->rw[r][tid]);
            s->usage[tid] = us * ret;
            float ss = 0.f;
#pragma unroll 8
            for (int w = 0; w < WWq; w++) { float v = s->mem[tid][w]; ss += v * v; }
            s->norms[tid] = sqrtf(ss);
        } else if (tid < 160) {
            int l = tid - 128;
            float p = s->wkey[l]*s->wkey[l] + s->wkey[l+32]*s->wkey[l+32];
            p = warp_sum(p);
            if (l == 0) s->scal[S_KN] = sqrtf(p);
        } else if (tid < 164) {
            int r = tid - 160; float ss = 0.f;
            for (int w = 0; w < WWq; w++) ss += s->rkeys[r][w]*s->rkeys[r][w];
            s->rknorm[r] = sqrtf(ss);
        }
        __syncthreads();

        // ---- write content weights (old mem) ----
        if (tid < 128) {
            float d = 0.f;
#pragma unroll 8
            for (int w = 0; w < WWq; w++) d += s->wkey[w] * s->mem[tid][w];
            s->wc[tid] = d / ((s->norms[tid] + EPSq) * (s->scal[S_KN] + EPSq)) * s->scal[S_WSTR];
        }
        __syncthreads();
        if (tid < 32) {
            float v0 = s->wc[tid], v1 = s->wc[tid+32], v2 = s->wc[tid+64], v3 = s->wc[tid+96];
            float mx = warp_max(fmaxf(fmaxf(v0, v1), fmaxf(v2, v3)));
            v0 = expf(v0-mx); v1 = expf(v1-mx); v2 = expf(v2-mx); v3 = expf(v3-mx);
            float inv = 1.f / warp_sum(v0 + v1 + v2 + v3);
            s->wc[tid] = v0*inv; s->wc[tid+32] = v1*inv; s->wc[tid+64] = v2*inv; s->wc[tid+96] = v3*inv;
        }
        __syncthreads();

        // ---- allocation: stable rank + cumprod scan ----
        if (tid < 128) s->u[tid] = DELTAq + (1.f - DELTAq) * s->usage[tid];
        __syncthreads();
        if (tid < 128) {
            float ui = s->u[tid]; int rk = 0;
            for (int j = 0; j < 128; j++) {
                float uj = s->u[j];
                rk += (uj < ui) || (uj == ui && j < tid);
            }
            s->rank[tid] = rk;
            s->su[rk] = ui;
        }
        __syncthreads();
        if (tid < 128) s->pe[tid] = s->su[tid];
        __syncthreads();
        for (int d = 1; d < 128; d <<= 1) {
            float v = 1.f;
            if (tid < 128 && tid >= d) v = s->pe[tid - d];
            __syncthreads();
            if (tid < 128 && tid >= d) s->pe[tid] *= v;
            __syncthreads();
        }
        if (tid < 128) {
            int rk = s->rank[tid];
            float excl = rk ? s->pe[rk - 1] : 1.f;
            float alloc = (1.f - s->u[tid]) * excl;
            float ag = s->scal[S_AG], wg = s->scal[S_WG];
            s->ww[tid] = wg * (ag * alloc + (1.f - ag) * s->wc[tid]);
        }
        __syncthreads();
        if (tid < 32) {
            float v = s->ww[tid] + s->ww[tid+32] + s->ww[tid+64] + s->ww[tid+96];
            v = warp_sum(v);
            if (tid == 0) s->scal[S_SWW] = v;
        }
        __syncthreads();

        // ---- mem write + link update (both need old prec only in link) ----
        {
            int w = tid & 63, ng = tid >> 6;
            for (int i = 0; i < 32; i++) {
                int n = ng * 32 + i;
                float wwn = s->ww[n];
                s->mem[n][w] = s->mem[n][w] * (1.f - wwn * s->erase[w]) + wwn * s->wvec[w];
            }
        }
        {
            int i = tid >> 1, j0 = (tid & 1) * 64;
            float wwi = s->ww[i];
            for (int jj = 0; jj < 64; jj++) {
                int j = j0 + jj;
                float l = (1.f - wwi - s->ww[j]) * s->link[i][j] + wwi * s->prec[j];
                s->link[i][j] = (i == j) ? 0.f : l;
            }
        }
        __syncthreads();
        if (tid < 128) {
            s->prec[tid] = (1.f - s->scal[S_SWW]) * s->prec[tid] + s->ww[tid];
            float ss = 0.f;
#pragma unroll 8
            for (int w = 0; w < WWq; w++) { float v = s->mem[tid][w]; ss += v * v; }
            s->norms[tid] = sqrtf(ss);
        }
        __syncthreads();

        // ---- read content (new mem) ----
        for (int p = tid; p < 512; p += 256) {
            int r = p >> 7, n = p & 127;
            float d = 0.f;
#pragma unroll 8
            for (int w = 0; w < WWq; w++) d += s->rkeys[r][w] * s->mem[n][w];
            s->rc[r][n] = d / ((s->norms[n] + EPSq) * (s->rknorm[r] + EPSq)) * s->rstr[r];
        }
        __syncthreads();
        if (tid < 128) {
            int r = tid >> 5, l = tid & 31;
            float v0 = s->rc[r][l], v1 = s->rc[r][l+32], v2 = s->rc[r][l+64], v3 = s->rc[r][l+96];
            float mx = warp_max(fmaxf(fmaxf(v0, v1), fmaxf(v2, v3)));
            v0 = expf(v0-mx); v1 = expf(v1-mx); v2 = expf(v2-mx); v3 = expf(v3-mx);
            float inv = 1.f / warp_sum(v0 + v1 + v2 + v3);
            s->rc[r][l] = v0*inv; s->rc[r][l+32] = v1*inv; s->rc[r][l+64] = v2*inv; s->rc[r][l+96] = v3*inv;
        }
        __syncthreads();

        // ---- fwd/bwd (old rw, new link) ----
        for (int p = tid; p < 512; p += 256) {
            int r = p >> 7, n = p & 127;
            float f = 0.f, bw = 0.f;
#pragma unroll 4
            for (int m = 0; m < 128; m++) {
                float rv = s->rw[r][m];
                f  += rv * s->link[n][m];
                bw += rv * s->link[m][n];
            }
            s->fwd[r][n] = f; s->bwd[r][n] = bw;
        }
        __syncthreads();
        for (int p = tid; p < 512; p += 256) {
            int r = p >> 7, n = p & 127;
            s->rw2[r][n] = s->modes[r][0]*s->bwd[r][n] + s->modes[r][1]*s->rc[r][n] + s->modes[r][2]*s->fwd[r][n];
        }
        __syncthreads();
        for (int p = tid; p < 512; p += 256) { int r = p >> 7, n = p & 127; s->rw[r][n] = s->rw2[r][n]; }
        __syncthreads();

        // ---- read vectors -> cat[512:768] ----
        {
            int r = tid >> 6, w = tid & 63;
            float acc = 0.f;
#pragma unroll 4
            for (int n = 0; n < 128; n++) acc += s->rw[r][n] * s->mem[n][w];
            cat[((size_t)t * BB + b) * CATW + 512 + tid] = acc;
        }
        __syncthreads();
    }
}

__global__ void gather_hid(float* __restrict__ out, const int* __restrict__ lens) {
    int b = blockIdx.x, i = threadIdx.x;
    int t = lens[b] - 1;
    out[(size_t)TT * BB * IDIMq + (size_t)b * IDIMq + i] = out[((size_t)t * BB + b) * IDIMq + i];
}

extern "C" void kernel_launch(void* const* d_in, const int* in_sizes, int n_in,
                              void* d_out, int out_size) {
    const float* embs = (const float*)d_in[0];
    const int*   lens = (const int*)  d_in[1];
    const float* Wih0 = (const float*)d_in[2];
    const float* Whh0 = (const float*)d_in[3];
    const float* bih0 = (const float*)d_in[4];
    const float* bhh0 = (const float*)d_in[5];
    const float* Wih1 = (const float*)d_in[6];
    const float* Whh1 = (const float*)d_in[7];
    const float* bih1 = (const float*)d_in[8];
    const float* bhh1 = (const float*)d_in[9];
    const float* Wxi  = (const float*)d_in[10];
    const float* bxi  = (const float*)d_in[11];
    const float* Wout = (const float*)d_in[12];
    const float* bout = (const float*)d_in[13];
    float* out = (float*)d_out;

    float *G, *h0, *h1, *c0, *c1, *cat, *xi;
    cudaGetSymbolAddress((void**)&G,   g_G);
    cudaGetSymbolAddress((void**)&h0,  g_h0);
    cudaGetSymbolAddress((void**)&h1,  g_h1);
    cudaGetSymbolAddress((void**)&c0,  g_c0);
    cudaGetSymbolAddress((void**)&c1,  g_c1);
    cudaGetSymbolAddress((void**)&cat, g_cat);
    cudaGetSymbolAddress((void**)&xi,  g_xi);

    cudaFuncSetAttribute(memory_kernel, cudaFuncAttributeMaxDynamicSharedMemorySize,
                         (int)sizeof(MemSmem));

    zero_c_kernel<<<64, 512>>>();

    // Gih0 = embs @ Wih0[:, :256]^T + bih0 + bhh0   (zeros_read contributes nothing)
    sgemm_bt<<<dim3(16, 64), 256>>>(embs, IDIMq, Wih0, CDIMq, G, 2048, bih0, bhh0, 2048, IDIMq);

    for (int t = 0; t < TT; t++) {
        lstm_step<<<dim3(32, 4), 256>>>(
            G + (size_t)t * BB * 2048,
            t ? h0 + (size_t)(t - 1) * BB * CDIMq : nullptr,
            Whh0, h0 + (size_t)t * BB * CDIMq, c0, nullptr);
    }

    // Gih1 = h0 @ Wih1^T + bih1 + bhh1
    sgemm_bt<<<dim3(16, 64), 256>>>(h0, CDIMq, Wih1, CDIMq, G, 2048, bih1, bhh1, 2048, CDIMq);

    for (int t = 0; t < TT; t++) {
        lstm_step<<<dim3(32, 4), 256>>>(
            G + (size_t)t * BB * 2048,
            t ? h1 + (size_t)((t - 1) & 1) * BB * CDIMq : nullptr,
            Whh1, h1 + (size_t)(t & 1) * BB * CDIMq, c1,
            cat + (size_t)t * BB * CATW);
    }

    // xi = clip(h1) @ Wxi^T + bxi   (clip(h1) is cat[:, :512], row stride CATW)
    sgemm_bt<<<dim3(4, 64), 256>>>(cat, CATW, Wxi, CDIMq, xi, IFACEq, bxi, nullptr, IFACEq, CDIMq);

    memory_kernel<<<64, 256, sizeof(MemSmem)>>>(xi, cat);

    // y = cat @ Wout^T + bout  -> d_out[0 : T*B*256)
    sgemm_bt<<<dim3(2, 64), 256>>>(cat, CATW, Wout, CATW, out, IDIMq, bout, nullptr, IDIMq, CATW);

    gather_hid<<<64, 256>>>(out, lens);
}

// round 4
// speedup vs baseline: 1.6652x; 1.6652x over previous
#include <cuda_runtime.h>
#include <math.h>
#include <stdint.h>

#define TT     128
#define BB     64
#define IDIMq  256
#define CDIMq  512
#define RRq    4
#define NNq    128
#define WWq    64
#define IFACEq 471
#define EPSq   1e-6f
#define DELTAq 5e-6f
#define CATW   768
#define NBLK   128

// ---------------- static device scratch ----------------
__device__ float g_G   [(size_t)TT * BB * 4 * CDIMq];
__device__ float g_h0  [(size_t)TT * BB * CDIMq];
__device__ float g_h1  [(size_t)TT * BB * CDIMq];
__device__ float g_cat [(size_t)TT * BB * CATW];
__device__ float g_xi  [(size_t)TT * BB * IFACEq];
__device__ unsigned g_bar_cnt = 0;
__device__ unsigned g_bar_gen = 0;

__device__ __forceinline__ float sigm(float x)  { return 1.f / (1.f + expf(-x)); }
__device__ __forceinline__ float splus(float x) { return fmaxf(x, 0.f) + log1pf(expf(-fabsf(x))); }
__device__ __forceinline__ float warp_sum(float v) {
#pragma unroll
    for (int o = 16; o; o >>= 1) v += __shfl_xor_sync(0xffffffffu, v, o);
    return v;
}
__device__ __forceinline__ float warp_max(float v) {
#pragma unroll
    for (int o = 16; o; o >>= 1) v = fmaxf(v, __shfl_xor_sync(0xffffffffu, v, o));
    return v;
}

// ---------------- two-phase grid barrier (all NBLK blocks co-resident) ----------------
__device__ __forceinline__ void grid_sync() {
    __syncthreads();
    if (threadIdx.x == 0) {
        __threadfence();
        unsigned gen = *(volatile unsigned*)&g_bar_gen;
        unsigned arr = atomicAdd(&g_bar_cnt, 1);
        if (arr == NBLK - 1) {
            atomicExch(&g_bar_cnt, 0);
            __threadfence();
            atomicExch(&g_bar_gen, gen + 1);
        } else {
            while (*(volatile unsigned*)&g_bar_gen == gen) { }
        }
        __threadfence();
    }
    __syncthreads();
}

// ---------------- SGEMM: C[M,N] = A[M,K] @ B[N,K]^T + bias1 (+bias2) ----------------
__global__ void __launch_bounds__(256) sgemm_bt(
    const float* __restrict__ A, int lda,
    const float* __restrict__ B, int ldb,
    float* __restrict__ C, int ldc,
    const float* __restrict__ bias1, const float* __restrict__ bias2,
    int N, int K)
{
    __shared__ float As[8][128];
    __shared__ float Bs[8][128];
    const int m0 = blockIdx.y * 128, n0 = blockIdx.x * 128;
    const int tid = threadIdx.x;
    const int lrow = tid >> 1;
    const int lk = (tid & 1) * 4;
    const int tx = tid & 15, ty = tid >> 4;

    float acc[8][8];
#pragma unroll
    for (int i = 0; i < 8; i++)
#pragma unroll
        for (int j = 0; j < 8; j++) acc[i][j] = 0.f;

    for (int k0 = 0; k0 < K; k0 += 8) {
        float4 av = *(const float4*)(A + (size_t)(m0 + lrow) * lda + k0 + lk);
        As[lk + 0][lrow] = av.x; As[lk + 1][lrow] = av.y;
        As[lk + 2][lrow] = av.z; As[lk + 3][lrow] = av.w;
        int nr = n0 + lrow;
        float4 bv = make_float4(0.f, 0.f, 0.f, 0.f);
        if (nr < N) bv = *(const float4*)(B + (size_t)nr * ldb + k0 + lk);
        Bs[lk + 0][lrow] = bv.x; Bs[lk + 1][lrow] = bv.y;
        Bs[lk + 2][lrow] = bv.z; Bs[lk + 3][lrow] = bv.w;
        __syncthreads();
#pragma unroll
        for (int k = 0; k < 8; k++) {
            float4 a0 = *(float4*)&As[k][ty * 8 + 0];
            float4 a1 = *(float4*)&As[k][ty * 8 + 4];
            float4 b0 = *(float4*)&Bs[k][tx * 8 + 0];
            float4 b1 = *(float4*)&Bs[k][tx * 8 + 4];
            float ar[8] = {a0.x, a0.y, a0.z, a0.w, a1.x, a1.y, a1.z, a1.w};
            float br[8] = {b0.x, b0.y, b0.z, b0.w, b1.x, b1.y, b1.z, b1.w};
#pragma unroll
            for (int i = 0; i < 8; i++)
#pragma unroll
                for (int j = 0; j < 8; j++) acc[i][j] += ar[i] * br[j];
        }
        __syncthreads();
    }
#pragma unroll
    for (int i = 0; i < 8; i++) {
        int m = m0 + ty * 8 + i;
#pragma unroll
        for (int j = 0; j < 8; j++) {
            int n = n0 + tx * 8 + j;
            if (n < N) {
                float v = acc[i][j] + bias1[n];
                if (bias2) v += bias2[n];
                C[(size_t)m * ldc + n] = v;
            }
        }
    }
}

// ---------------- persistent LSTM layer: all 128 steps, one kernel ----------------
// 128 blocks x 256 threads; block owns 4 h-features (16 gate-rows of Whh, smem-resident).
// Per step: stage h(t-1) -> smem, 8x8-tile matvec with 16-way k-split, reduce,
// gates (c in registers), write h, grid barrier.
#define WPITCH 520
#define HPITCH 520
#define WSM_SZ 8320
#define HSM_SZ 33360
#define RSM_SZ 8192
#define PSM_FLOATS (WSM_SZ + HSM_SZ + RSM_SZ)

__global__ void __launch_bounds__(256, 1) lstm_persist(
    const float* __restrict__ Gpre_all,  // [TT][BB][2048] (ih + both biases)
    const float* __restrict__ Whh,       // [2048][512]
    float*       hhist,                  // [TT][BB][512]
    float*       clipout)                // null or g_cat base
{
    extern __shared__ float sm[];
    float* Wsm = sm;
    float* Hsm = sm + WSM_SZ;
    float* Rsm = sm + WSM_SZ + HSM_SZ;

    const int tid = threadIdx.x, bid = blockIdx.x;
    const int warp = tid >> 5, lane = tid & 31;
    const int tile = lane & 15, sub = lane >> 4;
    const int r0 = (tile >> 3) * 8, b0 = (tile & 7) * 8;
    const int kb = warp * 64 + sub * 4;
    const int wbase = r0 * WPITCH + (r0 >> 3) * 8;
    const int hbase = b0 * HPITCH + (b0 >> 3) * 12;

    // stage this block's 16 gate-rows of Whh once (row r -> Whh[g*512 + bid*4 + jl])
    for (int idx = tid; idx < 16 * 128; idx += 256) {
        int r = idx >> 7, kq = idx & 127;
        int grow = (r >> 2) * 512 + bid * 4 + (r & 3);
        *(float4*)&Wsm[r * WPITCH + (r >> 3) * 8 + kq * 4] =
            *(const float4*)&Whh[(size_t)grow * 512 + kq * 4];
    }

    const int jl = tid >> 6;        // 0..3 local feature
    const int bb = tid & 63;        // batch
    const int jf = bid * 4 + jl;    // global feature
    float c = 0.f;

    for (int t = 0; t < TT; t++) {
        // ---- stage h(t-1) into skewed smem ----
        if (t == 0) {
            for (int idx = tid; idx < 64 * 128; idx += 256) {
                int b = idx >> 7, kq = idx & 127;
                *(float4*)&Hsm[b * HPITCH + (b >> 3) * 12 + kq * 4] = make_float4(0.f, 0.f, 0.f, 0.f);
            }
        } else {
            const float4* hsrc = (const float4*)(hhist + (size_t)(t - 1) * BB * 512);
            for (int idx = tid; idx < 64 * 128; idx += 256) {
                int b = idx >> 7, kq = idx & 127;
                *(float4*)&Hsm[b * HPITCH + (b >> 3) * 12 + kq * 4] = hsrc[b * 128 + kq];
            }
        }
        __syncthreads();

        // ---- 8x8 register-tile matvec over this thread's k-chunk ----
        float acc[8][8];
#pragma unroll
        for (int i = 0; i < 8; i++)
#pragma unroll
            for (int j = 0; j < 8; j++) acc[i][j] = 0.f;

#pragma unroll
        for (int j8 = 0; j8 < 8; j8++) {
            const int k = kb + j8 * 8;
            const float* wp = &Wsm[wbase + k];
            const float* hp = &Hsm[hbase + k];
            float4 wv[8], hv[8];
#pragma unroll
            for (int i = 0; i < 8; i++) wv[i] = *(const float4*)(wp + i * WPITCH);
#pragma unroll
            for (int i = 0; i < 8; i++) hv[i] = *(const float4*)(hp + i * HPITCH);
#pragma unroll
            for (int i = 0; i < 8; i++)
#pragma unroll
                for (int j = 0; j < 8; j++)
                    acc[i][j] += wv[i].x * hv[j].x + wv[i].y * hv[j].y
                               + wv[i].z * hv[j].z + wv[i].w * hv[j].w;
        }

        // ---- reduce sub halves in-warp, then across warps via smem ----
#pragma unroll
        for (int i = 0; i < 8; i++)
#pragma unroll
            for (int j = 0; j < 8; j++)
                acc[i][j] += __shfl_xor_sync(0xffffffffu, acc[i][j], 16);

        if (lane < 16) {
#pragma unroll
            for (int i = 0; i < 8; i++)
#pragma unroll
                for (int j = 0; j < 8; j++)
                    Rsm[warp * 1024 + (r0 + i) * 64 + (b0 + j)] = acc[i][j];
        }
        __syncthreads();

        // ---- final: sum 8 warp-partials, add Gpre, gates ----
        float g4[4];
#pragma unroll
        for (int g = 0; g < 4; g++) {
            int r = g * 4 + jl;
            float s = 0.f;
#pragma unroll
            for (int w = 0; w < 8; w++) s += Rsm[w * 1024 + r * 64 + bb];
            g4[g] = s;
        }
        const float* gp = Gpre_all + ((size_t)t * BB + bb) * 2048 + jf;
        float gi = g4[0] + gp[0];
        float gf = g4[1] + gp[512];
        float gg = g4[2] + gp[1024];
        float go = g4[3] + gp[1536];
        c = sigm(gf) * c + sigm(gi) * tanhf(gg);
        float h = sigm(go) * tanhf(c);
        hhist[((size_t)t * BB + bb) * 512 + jf] = h;
        if (clipout) clipout[((size_t)t * BB + bb) * CATW + jf] = fminf(fmaxf(h, -20.f), 20.f);

        if (t + 1 < TT) grid_sync();
    }
}

// ---------------- DNC memory module (unchanged from R2) ----------------
struct MemSmem {
    float mem[NNq][WWq + 1];
    float link[NNq][NNq + 1];
    float prec[NNq], usage[NNq], ww[NNq];
    float rw[RRq][NNq], rw2[RRq][NNq], fwd[RRq][NNq], bwd[RRq][NNq], rc[RRq][NNq];
    float wc[NNq], u[NNq], su[NNq], pe[NNq], norms[NNq];
    int   rank[NNq];
    float rkeys[RRq][WWq];
    float wkey[WWq], wvec[WWq], erase[WWq];
    float rstr[RRq], fg[RRq], rknorm[RRq];
    float modes[RRq][3];
    float scal[8];
};
#define S_WSTR 0
#define S_AG   1
#define S_WG   2
#define S_KN   3
#define S_SWW  4

__global__ void __launch_bounds__(256) memory_kernel(
    const float* __restrict__ xi_all, float* __restrict__ cat)
{
    extern __shared__ __align__(16) char smraw[];
    MemSmem* s = (MemSmem*)smraw;
    const int b = blockIdx.x, tid = threadIdx.x;

    for (int i = tid; i < (int)(sizeof(MemSmem) / 4); i += 256) ((float*)smraw)[i] = 0.f;
    __syncthreads();

    for (int t = 0; t < TT; t++) {
        const float* xi = xi_all + ((size_t)t * BB + b) * IFACEq;

        { int r = tid >> 6, w = tid & 63; s->rkeys[r][w] = tanhf(xi[tid]); }
        if (tid < 64) {
            s->wkey[tid]  = tanhf(xi[260 + tid]);
            s->erase[tid] = sigm (xi[325 + tid]);
            s->wvec[tid]  = tanhf(xi[389 + tid]);
        } else if (tid < 68) s->rstr[tid - 64] = splus(xi[256 + tid - 64]);
        else if (tid < 72)   s->fg[tid - 68]   = sigm (xi[453 + tid - 68]);
        else if (tid == 72)  s->scal[S_WSTR]   = splus(xi[324]);
        else if (tid == 73)  s->scal[S_AG]     = sigm (xi[457]);
        else if (tid == 74)  s->scal[S_WG]     = sigm (xi[458]);
        else if (tid >= 80 && tid < 84) {
            int r = tid - 80;
            float x0 = xi[459 + 3*r], x1 = xi[460 + 3*r], x2 = xi[461 + 3*r];
            float m = fmaxf(x0, fmaxf(x1, x2));
            float e0 = expf(x0 - m), e1 = expf(x1 - m), e2 = expf(x2 - m);
            float inv = 1.f / (e0 + e1 + e2);
            s->modes[r][0] = e0*inv; s->modes[r][1] = e1*inv; s->modes[r][2] = e2*inv;
        }
        __syncthreads();

        if (tid < 128) {
            float us = s->usage[tid] + (1.f - s->usage[tid]) * s->ww[tid];
            float ret = 1.f;
#pragma unroll
            for (int r = 0; r < RRq; r++) ret *= (1.f - s->fg[r] * s->rw[r][tid]);
            s->usage[tid] = us * ret;
            float ss = 0.f;
#pragma unroll 8
            for (int w = 0; w < WWq; w++) { float v = s->mem[tid][w]; ss += v * v; }
            s->norms[tid] = sqrtf(ss);
        } else if (tid < 160) {
            int l = tid - 128;
            float p = s->wkey[l]*s->wkey[l] + s->wkey[l+32]*s->wkey[l+32];
            p = warp_sum(p);
            if (l == 0) s->scal[S_KN] = sqrtf(p);
        } else if (tid < 164) {
            int r = tid - 160; float ss = 0.f;
            for (int w = 0; w < WWq; w++) ss += s->rkeys[r][w]*s->rkeys[r][w];
            s->rknorm[r] = sqrtf(ss);
        }
        __syncthreads();

        if (tid < 128) {
            float d = 0.f;
#pragma unroll 8
            for (int w = 0; w < WWq; w++) d += s->wkey[w] * s->mem[tid][w];
            s->wc[tid] = d / ((s->norms[tid] + EPSq) * (s->scal[S_KN] + EPSq)) * s->scal[S_WSTR];
        }
        __syncthreads();
        if (tid < 32) {
            float v0 = s->wc[tid], v1 = s->wc[tid+32], v2 = s->wc[tid+64], v3 = s->wc[tid+96];
            float mx = warp_max(fmaxf(fmaxf(v0, v1), fmaxf(v2, v3)));
            v0 = expf(v0-mx); v1 = expf(v1-mx); v2 = expf(v2-mx); v3 = expf(v3-mx);
            float inv = 1.f / warp_sum(v0 + v1 + v2 + v3);
            s->wc[tid] = v0*inv; s->wc[tid+32] = v1*inv; s->wc[tid+64] = v2*inv; s->wc[tid+96] = v3*inv;
        }
        __syncthreads();

        if (tid < 128) s->u[tid] = DELTAq + (1.f - DELTAq) * s->usage[tid];
        __syncthreads();
        if (tid < 128) {
            float ui = s->u[tid]; int rk = 0;
            for (int j = 0; j < 128; j++) {
                float uj = s->u[j];
                rk += (uj < ui) || (uj == ui && j < tid);
            }
            s->rank[tid] = rk;
            s->su[rk] = ui;
        }
        __syncthreads();
        if (tid < 128) s->pe[tid] = s->su[tid];
        __syncthreads();
        for (int d = 1; d < 128; d <<= 1) {
            float v = 1.f;
            if (tid < 128 && tid >= d) v = s->pe[tid - d];
            __syncthreads();
            if (tid < 128 && tid >= d) s->pe[tid] *= v;
            __syncthreads();
        }
        if (tid < 128) {
            int rk = s->rank[tid];
            float excl = rk ? s->pe[rk - 1] : 1.f;
            float alloc = (1.f - s->u[tid]) * excl;
            float ag = s->scal[S_AG], wg = s->scal[S_WG];
            s->ww[tid] = wg * (ag * alloc + (1.f - ag) * s->wc[tid]);
        }
        __syncthreads();
        if (tid < 32) {
            float v = s->ww[tid] + s->ww[tid+32] + s->ww[tid+64] + s->ww[tid+96];
            v = warp_sum(v);
            if (tid == 0) s->scal[S_SWW] = v;
        }
        __syncthreads();

        {
            int w = tid & 63, ng = tid >> 6;
            for (int i = 0; i < 32; i++) {
                int n = ng * 32 + i;
                float wwn = s->ww[n];
                s->mem[n][w] = s->mem[n][w] * (1.f - wwn * s->erase[w]) + wwn * s->wvec[w];
            }
        }
        {
            int i = tid >> 1, j0 = (tid & 1) * 64;
            float wwi = s->ww[i];
            for (int jj = 0; jj < 64; jj++) {
                int j = j0 + jj;
                float l = (1.f - wwi - s->ww[j]) * s->link[i][j] + wwi * s->prec[j];
                s->link[i][j] = (i == j) ? 0.f : l;
            }
        }
        __syncthreads();
        if (tid < 128) {
            s->prec[tid] = (1.f - s->scal[S_SWW]) * s->prec[tid] + s->ww[tid];
            float ss = 0.f;
#pragma unroll 8
            for (int w = 0; w < WWq; w++) { float v = s->mem[tid][w]; ss += v * v; }
            s->norms[tid] = sqrtf(ss);
        }
        __syncthreads();

        for (int p = tid; p < 512; p += 256) {
            int r = p >> 7, n = p & 127;
            float d = 0.f;
#pragma unroll 8
            for (int w = 0; w < WWq; w++) d += s->rkeys[r][w] * s->mem[n][w];
            s->rc[r][n] = d / ((s->norms[n] + EPSq) * (s->rknorm[r] + EPSq)) * s->rstr[r];
        }
        __syncthreads();
        if (tid < 128) {
            int r = tid >> 5, l = tid & 31;
            float v0 = s->rc[r][l], v1 = s->rc[r][l+32], v2 = s->rc[r][l+64], v3 = s->rc[r][l+96];
            float mx = warp_max(fmaxf(fmaxf(v0, v1), fmaxf(v2, v3)));
            v0 = expf(v0-mx); v1 = expf(v1-mx); v2 = expf(v2-mx); v3 = expf(v3-mx);
            float inv = 1.f / warp_sum(v0 + v1 + v2 + v3);
            s->rc[r][l] = v0*inv; s->rc[r][l+32] = v1*inv; s->rc[r][l+64] = v2*inv; s->rc[r][l+96] = v3*inv;
        }
        __syncthreads();

        for (int p = tid; p < 512; p += 256) {
            int r = p >> 7, n = p & 127;
            float f = 0.f, bw = 0.f;
#pragma unroll 4
            for (int m = 0; m < 128; m++) {
                float rv = s->rw[r][m];
                f  += rv * s->link[n][m];
                bw += rv * s->link[m][n];
            }
            s->fwd[r][n] = f; s->bwd[r][n] = bw;
        }
        __syncthreads();
        for (int p = tid; p < 512; p += 256) {
            int r = p >> 7, n = p & 127;
            s->rw2[r][n] = s->modes[r][0]*s->bwd[r][n] + s->modes[r][1]*s->rc[r][n] + s->modes[r][2]*s->fwd[r][n];
        }
        __syncthreads();
        for (int p = tid; p < 512; p += 256) { int r = p >> 7, n = p & 127; s->rw[r][n] = s->rw2[r][n]; }
        __syncthreads();

        {
            int r = tid >> 6, w = tid & 63;
            float acc = 0.f;
#pragma unroll 4
            for (int n = 0; n < 128; n++) acc += s->rw[r][n] * s->mem[n][w];
            cat[((size_t)t * BB + b) * CATW + 512 + tid] = acc;
        }
        __syncthreads();
    }
}

__global__ void gather_hid(float* __restrict__ out, const int* __restrict__ lens) {
    int b = blockIdx.x, i = threadIdx.x;
    int t = lens[b] - 1;
    out[(size_t)TT * BB * IDIMq + (size_t)b * IDIMq + i] = out[((size_t)t * BB + b) * IDIMq + i];
}

extern "C" void kernel_launch(void* const* d_in, const int* in_sizes, int n_in,
                              void* d_out, int out_size) {
    const float* embs = (const float*)d_in[0];
    const int*   lens = (const int*)  d_in[1];
    const float* Wih0 = (const float*)d_in[2];
    const float* Whh0 = (const float*)d_in[3];
    const float* bih0 = (const float*)d_in[4];
    const float* bhh0 = (const float*)d_in[5];
    const float* Wih1 = (const float*)d_in[6];
    const float* Whh1 = (const float*)d_in[7];
    const float* bih1 = (const float*)d_in[8];
    const float* bhh1 = (const float*)d_in[9];
    const float* Wxi  = (const float*)d_in[10];
    const float* bxi  = (const float*)d_in[11];
    const float* Wout = (const float*)d_in[12];
    const float* bout = (const float*)d_in[13];
    float* out = (float*)d_out;

    float *G, *h0, *h1, *cat, *xi;
    cudaGetSymbolAddress((void**)&G,   g_G);
    cudaGetSymbolAddress((void**)&h0,  g_h0);
    cudaGetSymbolAddress((void**)&h1,  g_h1);
    cudaGetSymbolAddress((void**)&cat, g_cat);
    cudaGetSymbolAddress((void**)&xi,  g_xi);

    cudaFuncSetAttribute(memory_kernel, cudaFuncAttributeMaxDynamicSharedMemorySize,
                         (int)sizeof(MemSmem));
    cudaFuncSetAttribute(lstm_persist, cudaFuncAttributeMaxDynamicSharedMemorySize,
                         PSM_FLOATS * 4);

    // Gih0 = embs @ Wih0[:, :256]^T + bih0 + bhh0   (zeros_read contributes nothing)
    sgemm_bt<<<dim3(16, 64), 256>>>(embs, IDIMq, Wih0, CDIMq, G, 2048, bih0, bhh0, 2048, IDIMq);

    // layer 0: all 128 steps, one persistent kernel
    lstm_persist<<<NBLK, 256, PSM_FLOATS * 4>>>(G, Whh0, h0, nullptr);

    // Gih1 = h0 @ Wih1^T + bih1 + bhh1
    sgemm_bt<<<dim3(16, 64), 256>>>(h0, CDIMq, Wih1, CDIMq, G, 2048, bih1, bhh1, 2048, CDIMq);

    // layer 1: all 128 steps, one persistent kernel (also writes clip(h1) into cat)
    lstm_persist<<<NBLK, 256, PSM_FLOATS * 4>>>(G, Whh1, h1, cat);

    // xi = clip(h1) @ Wxi^T + bxi
    sgemm_bt<<<dim3(4, 64), 256>>>(cat, CATW, Wxi, CDIMq, xi, IFACEq, bxi, nullptr, IFACEq, CDIMq);

    memory_kernel<<<64, 256, sizeof(MemSmem)>>>(xi, cat);

    // y = cat @ Wout^T + bout
    sgemm_bt<<<dim3(2, 64), 256>>>(cat, CATW, Wout, CATW, out, IDIMq, bout, nullptr, IDIMq, CATW);

    gather_hid<<<64, 256>>>(out, lens);
}